// round 1
// baseline (speedup 1.0000x reference)
#include <cuda_runtime.h>
#include <cuda_bf16.h>

// RepeatLayers: variable-length repeat_interleave along axis 0.
//   encoder_h: [N=8192, D=1024] fp32
//   repeats:   [N] int32 in [0, 8)
//   out:       [sum(repeats), D] fp32
//
// Strategy: source-side scatter.
//   Kernel 1: single-block exclusive prefix sum of repeats -> g_offsets.
//   Kernel 2: one CTA per source row; load row once (float4/thread),
//             store it `rep` times at consecutive output row slots.

#define N_ROWS 8192
#define D_ELEMS 1024
#define D_VEC4 (D_ELEMS / 4)   // 256 float4 per row

__device__ int g_offsets[N_ROWS];   // exclusive prefix sum of repeats

// ---------------------------------------------------------------------------
// Kernel 1: exclusive prefix scan of 8192 int32 in one 1024-thread block.
// Each thread handles 8 contiguous elements.
// ---------------------------------------------------------------------------
__global__ __launch_bounds__(1024, 1)
void repeat_scan_kernel(const int* __restrict__ repeats) {
    __shared__ int warp_sums[32];

    const int t = threadIdx.x;          // 0..1023
    const int base = t * 8;

    // Sequential exclusive scan within the thread's 8 elements.
    int excl[8];
    int s = 0;
#pragma unroll
    for (int i = 0; i < 8; i++) {
        excl[i] = s;
        s += repeats[base + i];
    }

    // Inclusive warp scan of per-thread sums.
    const int lane = t & 31;
    const int wid = t >> 5;
    int x = s;
#pragma unroll
    for (int d = 1; d < 32; d <<= 1) {
        int y = __shfl_up_sync(0xFFFFFFFFu, x, d);
        if (lane >= d) x += y;
    }
    if (lane == 31) warp_sums[wid] = x;
    __syncthreads();

    // Warp 0 scans the 32 warp totals (inclusive).
    if (wid == 0) {
        int w = warp_sums[lane];
#pragma unroll
        for (int d = 1; d < 32; d <<= 1) {
            int y = __shfl_up_sync(0xFFFFFFFFu, w, d);
            if (lane >= d) w += y;
        }
        warp_sums[lane] = w;
    }
    __syncthreads();

    const int warp_off = (wid > 0) ? warp_sums[wid - 1] : 0;
    const int thread_excl = warp_off + (x - s);   // exclusive offset of this thread's chunk

#pragma unroll
    for (int i = 0; i < 8; i++) {
        g_offsets[base + i] = thread_excl + excl[i];
    }
}

// ---------------------------------------------------------------------------
// Kernel 2: one CTA per source row. 256 threads, one float4 each.
// Load the row once, store it `rep` times.
// ---------------------------------------------------------------------------
__global__ __launch_bounds__(256, 8)
void repeat_scatter_kernel(const float* __restrict__ src,
                           const int* __restrict__ repeats,
                           float* __restrict__ out) {
    const int row = blockIdx.x;
    const int rep = __ldg(&repeats[row]);
    if (rep == 0) return;

    const int t = threadIdx.x;     // 0..255
    const float4 v = reinterpret_cast<const float4*>(src)[(size_t)row * D_VEC4 + t];

    const int off = g_offsets[row];
    float4* o = reinterpret_cast<float4*>(out) + (size_t)off * D_VEC4 + t;

#pragma unroll 4
    for (int r = 0; r < rep; r++) {
        *o = v;
        o += D_VEC4;
    }
}

// ---------------------------------------------------------------------------
// Launch
// ---------------------------------------------------------------------------
extern "C" void kernel_launch(void* const* d_in, const int* in_sizes, int n_in,
                              void* d_out, int out_size) {
    // Defensive input resolution: encoder_h has N*D elements, repeats has N.
    const float* encoder_h;
    const int* repeats;
    if (in_sizes[0] == N_ROWS * D_ELEMS) {
        encoder_h = (const float*)d_in[0];
        repeats   = (const int*)d_in[1];
    } else {
        encoder_h = (const float*)d_in[1];
        repeats   = (const int*)d_in[0];
    }
    float* out = (float*)d_out;
    (void)n_in; (void)out_size;

    repeat_scan_kernel<<<1, 1024>>>(repeats);
    repeat_scatter_kernel<<<N_ROWS, 256>>>(encoder_h, repeats, out);
}

// round 2
// speedup vs baseline: 1.1304x; 1.1304x over previous
#include <cuda_runtime.h>
#include <cuda_bf16.h>

// RepeatLayers: variable-length repeat_interleave along axis 0.
//   encoder_h: [N=8192, D=1024] fp32
//   repeats:   [N] int32 in [0, 8)
//   out:       [sum(repeats), D] fp32
//
// R2 strategy:
//   Kernel 1 (scan): single-block exclusive prefix sum of repeats -> g_offsets,
//                    then cudaTriggerProgrammaticLaunchCompletion() for PDL.
//   Kernel 2 (scatter): launched with programmatic stream serialization (PDL).
//                    Each CTA issues its row LDG BEFORE cudaGridDependencySynchronize()
//                    so first-wave load latency overlaps the scan tail. Stores use
//                    __stcs (evict-first) so the 115MB output stream does not evict
//                    the 32MB input from L2 across graph replays.

#define N_ROWS 8192
#define D_ELEMS 1024
#define D_VEC4 (D_ELEMS / 4)   // 256 float4 per row

__device__ int g_offsets[N_ROWS];   // exclusive prefix sum of repeats

// ---------------------------------------------------------------------------
// Kernel 1: exclusive prefix scan of 8192 int32 in one 1024-thread block.
// ---------------------------------------------------------------------------
__global__ __launch_bounds__(1024, 1)
void repeat_scan_kernel(const int* __restrict__ repeats) {
    __shared__ int warp_sums[32];

    const int t = threadIdx.x;          // 0..1023
    const int base = t * 8;

    // Vector-load this thread's 8 elements (two int4).
    int4 a = reinterpret_cast<const int4*>(repeats)[t * 2 + 0];
    int4 b = reinterpret_cast<const int4*>(repeats)[t * 2 + 1];
    int vals[8] = {a.x, a.y, a.z, a.w, b.x, b.y, b.z, b.w};

    int excl[8];
    int s = 0;
#pragma unroll
    for (int i = 0; i < 8; i++) {
        excl[i] = s;
        s += vals[i];
    }

    // Inclusive warp scan of per-thread sums.
    const int lane = t & 31;
    const int wid = t >> 5;
    int x = s;
#pragma unroll
    for (int d = 1; d < 32; d <<= 1) {
        int y = __shfl_up_sync(0xFFFFFFFFu, x, d);
        if (lane >= d) x += y;
    }
    if (lane == 31) warp_sums[wid] = x;
    __syncthreads();

    if (wid == 0) {
        int w = warp_sums[lane];
#pragma unroll
        for (int d = 1; d < 32; d <<= 1) {
            int y = __shfl_up_sync(0xFFFFFFFFu, w, d);
            if (lane >= d) w += y;
        }
        warp_sums[lane] = w;
    }
    __syncthreads();

    const int warp_off = (wid > 0) ? warp_sums[wid - 1] : 0;
    const int thread_excl = warp_off + (x - s);

#pragma unroll
    for (int i = 0; i < 8; i++) {
        g_offsets[base + i] = thread_excl + excl[i];
    }

    // Make offsets visible, then fire the dependent launch early.
    __threadfence();
    __syncthreads();
    cudaTriggerProgrammaticLaunchCompletion();
}

// ---------------------------------------------------------------------------
// Kernel 2: one CTA per source row. 256 threads, one float4 each.
// Row load is issued BEFORE the PDL grid-dependency sync.
// ---------------------------------------------------------------------------
__global__ __launch_bounds__(256, 8)
void repeat_scatter_kernel(const float* __restrict__ src,
                           const int* __restrict__ repeats,
                           float* __restrict__ out) {
    const int row = blockIdx.x;
    const int t = threadIdx.x;     // 0..255

    // repeats is a harness input — not produced by the scan; safe pre-sync.
    const int rep = __ldg(&repeats[row]);
    if (rep == 0) return;

    // Issue the row load now; its DRAM latency overlaps the scan tail.
    const float4 v = reinterpret_cast<const float4*>(src)[(size_t)row * D_VEC4 + t];

    // Wait for the scan kernel's g_offsets to be visible.
    cudaGridDependencySynchronize();

    const int off = g_offsets[row];
    float4* o = reinterpret_cast<float4*>(out) + (size_t)off * D_VEC4 + t;

#pragma unroll 8
    for (int r = 0; r < rep; r++) {
        __stcs(o, v);            // evict-first: don't let output evict input in L2
        o += D_VEC4;
    }
}

// ---------------------------------------------------------------------------
// Launch
// ---------------------------------------------------------------------------
extern "C" void kernel_launch(void* const* d_in, const int* in_sizes, int n_in,
                              void* d_out, int out_size) {
    const float* encoder_h;
    const int* repeats;
    if (in_sizes[0] == N_ROWS * D_ELEMS) {
        encoder_h = (const float*)d_in[0];
        repeats   = (const int*)d_in[1];
    } else {
        encoder_h = (const float*)d_in[1];
        repeats   = (const int*)d_in[0];
    }
    float* out = (float*)d_out;
    (void)n_in; (void)out_size;

    repeat_scan_kernel<<<1, 1024>>>(repeats);

    // Scatter with programmatic dependent launch so it overlaps the scan tail.
    cudaLaunchAttribute attr[1];
    attr[0].id = cudaLaunchAttributeProgrammaticStreamSerialization;
    attr[0].val.programmaticStreamSerializationAllowed = 1;

    cudaLaunchConfig_t cfg = {};
    cfg.gridDim = dim3(N_ROWS, 1, 1);
    cfg.blockDim = dim3(256, 1, 1);
    cfg.dynamicSmemBytes = 0;
    cfg.stream = 0;
    cfg.attrs = attr;
    cfg.numAttrs = 1;

    cudaError_t e = cudaLaunchKernelEx(&cfg, repeat_scatter_kernel,
                                       encoder_h, repeats, out);
    if (e != cudaSuccess) {
        // Fallback: plain serialized launch (still correct).
        repeat_scatter_kernel<<<N_ROWS, 256>>>(encoder_h, repeats, out);
    }
}